// round 2
// baseline (speedup 1.0000x reference)
#include <cuda_runtime.h>

#define D      64
#define H      64
#define KTOT   129          // 2*D + 1
#define TPB    256
#define EPT    4            // edges per thread

// packed fp32x2 FMA (Blackwell): d = a*b + c on both lanes
__device__ __forceinline__ unsigned long long ffma2(unsigned long long a,
                                                    unsigned long long b,
                                                    unsigned long long c) {
    unsigned long long d;
    asm("fma.rn.f32x2 %0, %1, %2, %3;" : "=l"(d) : "l"(a), "l"(b), "l"(c));
    return d;
}

__device__ __forceinline__ unsigned long long dup2(float x) {
    unsigned int xi = __float_as_uint(x);
    unsigned long long r;
    asm("mov.b64 %0, {%1, %1};" : "=l"(r) : "r"(xi));
    return r;
}

__global__ __launch_bounds__(TPB)
void edge_mlp_kernel(const float* __restrict__ hc,   // [N_CUST, 64]
                     const float* __restrict__ hp,   // [N_PROD, 64]
                     const int*   __restrict__ src,  // [E]
                     const int*   __restrict__ dst,  // [E]
                     const float* __restrict__ W1,   // [129, 64]
                     const float* __restrict__ b1,   // [64]
                     const float* __restrict__ W2,   // [64]
                     const float* __restrict__ b2,   // [1]
                     float*       __restrict__ out,  // [E]
                     int E)
{
    __shared__ __align__(16) float sW1[KTOT * H];   // 33 KB
    __shared__ __align__(16) float sB1[H];
    __shared__ float sW2[H];
    __shared__ float sB2;

    for (int i = threadIdx.x; i < KTOT * H; i += TPB) sW1[i] = W1[i];
    if (threadIdx.x < H) { sW2[threadIdx.x] = W2[threadIdx.x]; sB1[threadIdx.x] = b1[threadIdx.x]; }
    if (threadIdx.x == 0) sB2 = b2[0];
    __syncthreads();

    const unsigned long long* sW1q = (const unsigned long long*)sW1;  // pairs along hidden
    const unsigned long long* sB1q = (const unsigned long long*)sB1;

    int e0 = blockIdx.x * (TPB * EPT) + threadIdx.x;

    #pragma unroll 1
    for (int it = 0; it < EPT; ++it) {
        int e = e0 + it * TPB;
        if (e >= E) break;   // e monotonically increasing -> break is safe

        int si = src[e];
        int ti = dst[e];
        const float4* h4 = (const float4*)(hc + (size_t)si * D);
        const float4* t4 = (const float4*)(hp + (size_t)ti * D);

        float x[KTOT];
        #pragma unroll
        for (int i = 0; i < D / 4; ++i) {
            float4 a = h4[i];
            x[4*i + 0] = a.x; x[4*i + 1] = a.y; x[4*i + 2] = a.z; x[4*i + 3] = a.w;
        }
        #pragma unroll
        for (int i = 0; i < D / 4; ++i) {
            float4 a = t4[i];
            x[D + 4*i + 0] = a.x; x[D + 4*i + 1] = a.y; x[D + 4*i + 2] = a.z; x[D + 4*i + 3] = a.w;
        }

        // cosine of normalized vectors (matches reference eps handling)
        float nh = 0.f, nt = 0.f, dp = 0.f;
        #pragma unroll
        for (int i = 0; i < D; ++i) {
            nh = fmaf(x[i],     x[i],     nh);
            nt = fmaf(x[D + i], x[D + i], nt);
            dp = fmaf(x[i],     x[D + i], dp);
        }
        float nhs  = sqrtf(nh);
        float nts  = sqrtf(nt);
        float invh = 1.0f / fmaxf(nhs, 1e-12f);
        float invt = 1.0f / fmaxf(nts, 1e-12f);
        float hnn  = nhs * invh;   // || hn ||  (== 1 unless degenerate)
        float tnn  = nts * invt;
        float cosv = (dp * invh * invt) / fmaxf(hnn * tnn, 1e-8f);
        x[2 * D] = cosv;

        // MLP: z = b2 + sum_j relu(b1_j + sum_k x_k W1[k][j]) * W2[j]
        float z = sB2;
        #pragma unroll
        for (int c = 0; c < 4; ++c) {                // 4 chunks of 16 hidden (8 f32x2 accs)
            unsigned long long acc[8];
            #pragma unroll
            for (int p = 0; p < 8; ++p) acc[p] = sB1q[c * 8 + p];

            #pragma unroll
            for (int k = 0; k < KTOT; ++k) {
                unsigned long long bx = dup2(x[k]);
                const ulonglong2* w = (const ulonglong2*)&sW1q[k * (H / 2) + c * 8];
                ulonglong2 w0 = w[0], w1 = w[1], w2 = w[2], w3 = w[3];
                acc[0] = ffma2(w0.x, bx, acc[0]);
                acc[1] = ffma2(w0.y, bx, acc[1]);
                acc[2] = ffma2(w1.x, bx, acc[2]);
                acc[3] = ffma2(w1.y, bx, acc[3]);
                acc[4] = ffma2(w2.x, bx, acc[4]);
                acc[5] = ffma2(w2.y, bx, acc[5]);
                acc[6] = ffma2(w3.x, bx, acc[6]);
                acc[7] = ffma2(w3.y, bx, acc[7]);
            }

            #pragma unroll
            for (int p = 0; p < 8; ++p) {
                float lo = __uint_as_float((unsigned int)(acc[p] & 0xffffffffULL));
                float hi = __uint_as_float((unsigned int)(acc[p] >> 32));
                z = fmaf(fmaxf(lo, 0.f), sW2[c * 16 + 2 * p],     z);
                z = fmaf(fmaxf(hi, 0.f), sW2[c * 16 + 2 * p + 1], z);
            }
        }

        out[e] = 1.0f / (1.0f + expf(-z));
    }
}

extern "C" void kernel_launch(void* const* d_in, const int* in_sizes, int n_in,
                              void* d_out, int out_size)
{
    const float* hc  = (const float*)d_in[0];
    const float* hp  = (const float*)d_in[1];
    const int*   src = (const int*)  d_in[2];
    const int*   dst = (const int*)  d_in[3];
    const float* W1  = (const float*)d_in[4];
    const float* b1  = (const float*)d_in[5];
    const float* W2  = (const float*)d_in[6];
    const float* b2  = (const float*)d_in[7];
    float* out = (float*)d_out;

    int E = in_sizes[2];
    int blocks = (E + TPB * EPT - 1) / (TPB * EPT);
    edge_mlp_kernel<<<blocks, TPB>>>(hc, hp, src, dst, W1, b1, W2, b2, out, E);
}

// round 4
// speedup vs baseline: 2.0613x; 2.0613x over previous
#include <cuda_runtime.h>
#include <cstdint>

#define D        64
#define H        64
#define KTOT     129        // 2*D + 1
#define KPAD     136        // 17 * 8
#define NKSTEP   17
#define TILE_M   256
#define TPB      256

#define XSTRIDE  137        // odd word stride -> conflict-free column access
#define BSTRIDE  137

// dynamic smem layout (bytes)
#define SM_X     0
#define SM_X_SZ  (TILE_M * XSTRIDE * 4)          // 140288
#define SM_B     (SM_X + SM_X_SZ)                // W1^T [64][137] tf32
#define SM_B_SZ  (H * BSTRIDE * 4)               // 35072
#define SM_B1    (SM_B + SM_B_SZ)                // 64 f32
#define SM_W2    (SM_B1 + 256)                   // 64 f32
#define SM_B2    (SM_W2 + 256)                   // 1 f32
#define SM_TOTAL (SM_B2 + 16)

__device__ __forceinline__ uint32_t f2tf32(float x) {
    uint32_t r;
    asm("cvt.rna.tf32.f32 %0, %1;" : "=r"(r) : "f"(x));
    return r;
}

__device__ __forceinline__ void mma_tf32(float c[4],
                                         uint32_t a0, uint32_t a1, uint32_t a2, uint32_t a3,
                                         uint32_t b0, uint32_t b1) {
    asm volatile(
        "mma.sync.aligned.m16n8k8.row.col.f32.tf32.tf32.f32 "
        "{%0,%1,%2,%3}, {%4,%5,%6,%7}, {%8,%9}, {%0,%1,%2,%3};"
        : "+f"(c[0]), "+f"(c[1]), "+f"(c[2]), "+f"(c[3])
        : "r"(a0), "r"(a1), "r"(a2), "r"(a3), "r"(b0), "r"(b1));
}

__global__ __launch_bounds__(TPB)
void edge_mlp_mma_kernel(const float* __restrict__ hc,
                         const float* __restrict__ hp,
                         const int*   __restrict__ src,
                         const int*   __restrict__ dst,
                         const float* __restrict__ W1,   // [129][64] row-major
                         const float* __restrict__ b1,
                         const float* __restrict__ W2,
                         const float* __restrict__ b2,
                         float*       __restrict__ out,
                         int E)
{
    extern __shared__ char smem[];
    uint32_t* sX  = (uint32_t*)(smem + SM_X);
    uint32_t* sB  = (uint32_t*)(smem + SM_B);
    float*    sB1 = (float*)(smem + SM_B1);
    float*    sW2 = (float*)(smem + SM_W2);
    float*    sB2 = (float*)(smem + SM_B2);

    const int tid  = threadIdx.x;
    const int wid  = tid >> 5;
    const int lane = tid & 31;

    // ---- gather one edge per thread ----
    const int e0 = blockIdx.x * TILE_M;
    const int e  = e0 + tid;
    const bool valid = (e < E);
    const int ec = valid ? e : (E - 1);
    const int si = src[ec];
    const int ti = dst[ec];

    float xh[D], xt[D];
    {
        const float4* h4 = (const float4*)(hc + (size_t)si * D);
        const float4* t4 = (const float4*)(hp + (size_t)ti * D);
        #pragma unroll
        for (int i = 0; i < D / 4; ++i) {
            float4 a = h4[i];
            xh[4*i] = a.x; xh[4*i+1] = a.y; xh[4*i+2] = a.z; xh[4*i+3] = a.w;
        }
        #pragma unroll
        for (int i = 0; i < D / 4; ++i) {
            float4 a = t4[i];
            xt[4*i] = a.x; xt[4*i+1] = a.y; xt[4*i+2] = a.z; xt[4*i+3] = a.w;
        }
    }

    // ---- stage weights (overlaps with gather latency) ----
    // zero B pad region first (cols >= 129); then fill after sync
    for (int i = tid; i < H * BSTRIDE; i += TPB) sB[i] = 0;
    if (tid < H) { sB1[tid] = b1[tid]; sW2[tid] = W2[tid]; }
    if (tid == 0) sB2[0] = b2[0];
    __syncthreads();
    for (int idx = tid; idx < KTOT * H; idx += TPB) {
        int k = idx >> 6;          // /64
        int n = idx & 63;
        sB[n * BSTRIDE + k] = f2tf32(W1[idx]);
    }

    // ---- cosine ----
    float nh = 0.f, nt = 0.f, dp = 0.f;
    #pragma unroll
    for (int i = 0; i < D; ++i) {
        nh = fmaf(xh[i], xh[i], nh);
        nt = fmaf(xt[i], xt[i], nt);
        dp = fmaf(xh[i], xt[i], dp);
    }
    float nhs = sqrtf(nh), nts = sqrtf(nt);
    float invh = 1.0f / fmaxf(nhs, 1e-12f);
    float invt = 1.0f / fmaxf(nts, 1e-12f);
    float hnn = nhs * invh, tnn = nts * invt;
    float cosv = (dp * invh * invt) / fmaxf(hnn * tnn, 1e-8f);

    // ---- stage activation row as tf32 ----
    {
        uint32_t* row = sX + tid * XSTRIDE;
        #pragma unroll
        for (int i = 0; i < D; ++i) row[i]     = f2tf32(xh[i]);
        #pragma unroll
        for (int i = 0; i < D; ++i) row[D + i] = f2tf32(xt[i]);
        row[2 * D] = f2tf32(cosv);
        #pragma unroll
        for (int i = KTOT; i < XSTRIDE; ++i) row[i] = 0;
    }
    __syncthreads();

    // ---- mainloop: per warp 32 rows (2 m-tiles), 8 n-tiles, 17 k-steps ----
    const int qrow  = lane >> 2;   // 0..7
    const int qlane = lane & 3;    // 0..3

    float acc[2][8][4];
    #pragma unroll
    for (int mt = 0; mt < 2; ++mt)
        #pragma unroll
        for (int nt = 0; nt < 8; ++nt)
            #pragma unroll
            for (int c = 0; c < 4; ++c) acc[mt][nt][c] = 0.f;

    const uint32_t* Xw = sX + (wid * 32) * XSTRIDE;
    const uint32_t* Xr0 = Xw + qrow * XSTRIDE;            // m-tile0 rows qrow / qrow+8
    const uint32_t* Bq  = sB + qrow * BSTRIDE;            // n = nt*8 + qrow

    #pragma unroll
    for (int s = 0; s < NKSTEP; ++s) {
        const int k0 = s * 8 + qlane;

        uint32_t bf0[8], bf1[8];
        #pragma unroll
        for (int nt = 0; nt < 8; ++nt) {
            bf0[nt] = Bq[nt * 8 * BSTRIDE + k0];
            bf1[nt] = Bq[nt * 8 * BSTRIDE + k0 + 4];
        }

        #pragma unroll
        for (int mt = 0; mt < 2; ++mt) {
            const uint32_t* Xm = Xr0 + mt * 16 * XSTRIDE;
            uint32_t a0 = Xm[k0];
            uint32_t a1 = Xm[8 * XSTRIDE + k0];
            uint32_t a2 = Xm[k0 + 4];
            uint32_t a3 = Xm[8 * XSTRIDE + k0 + 4];
            #pragma unroll
            for (int nt = 0; nt < 8; ++nt)
                mma_tf32(acc[mt][nt], a0, a1, a2, a3, bf0[nt], bf1[nt]);
        }
    }

    // ---- epilogue: h = relu(acc + b1); z = sum h*W2; quad reduce; sigmoid ----
    const float bias2 = sB2[0];
    #pragma unroll
    for (int mt = 0; mt < 2; ++mt) {
        #pragma unroll
        for (int rr = 0; rr < 2; ++rr) {
            float z = 0.f;
            #pragma unroll
            for (int nt = 0; nt < 8; ++nt) {
                int n0 = nt * 8 + 2 * qlane;
                float v0 = acc[mt][nt][2 * rr];
                float v1 = acc[mt][nt][2 * rr + 1];
                float h0 = fmaxf(v0 + sB1[n0], 0.f);
                float h1 = fmaxf(v1 + sB1[n0 + 1], 0.f);
                z = fmaf(h0, sW2[n0], z);
                z = fmaf(h1, sW2[n0 + 1], z);
            }
            z += __shfl_xor_sync(0xffffffffu, z, 1);
            z += __shfl_xor_sync(0xffffffffu, z, 2);
            if (qlane == 0) {
                int row = wid * 32 + mt * 16 + rr * 8 + qrow;
                int eo  = e0 + row;
                if (eo < E) {
                    float zz = z + bias2;
                    out[eo] = 1.0f / (1.0f + expf(-zz));
                }
            }
        }
    }
}

extern "C" void kernel_launch(void* const* d_in, const int* in_sizes, int n_in,
                              void* d_out, int out_size)
{
    const float* hc  = (const float*)d_in[0];
    const float* hp  = (const float*)d_in[1];
    const int*   src = (const int*)  d_in[2];
    const int*   dst = (const int*)  d_in[3];
    const float* W1  = (const float*)d_in[4];
    const float* b1  = (const float*)d_in[5];
    const float* W2  = (const float*)d_in[6];
    const float* b2  = (const float*)d_in[7];
    float* out = (float*)d_out;

    static int smem_set = 0;
    if (!smem_set) {
        cudaFuncSetAttribute(edge_mlp_mma_kernel,
                             cudaFuncAttributeMaxDynamicSharedMemorySize, SM_TOTAL);
        smem_set = 1;
    }

    int E = in_sizes[2];
    int blocks = (E + TILE_M - 1) / TILE_M;
    edge_mlp_mma_kernel<<<blocks, TPB, SM_TOTAL>>>(hc, hp, src, dst, W1, b1, W2, b2, out, E);
}

// round 5
// speedup vs baseline: 3.2197x; 1.5619x over previous
#include <cuda_runtime.h>
#include <cstdint>

#define D        64
#define H        64
#define KTOT     129
#define NKSTEP   17          // K padded to 136
#define TILE_M   128
#define TPB      128

#define XSTRIDE  140         // words; 140%32=12 -> ldmatrix rows conflict-free; 560B %16==0
#define BSTRIDE  140

// dynamic smem layout (bytes)
#define SM_X     0
#define SM_X_SZ  (TILE_M * XSTRIDE * 4)         // 71680
#define SM_B     (SM_X + SM_X_SZ)
#define SM_B_SZ  (H * BSTRIDE * 4)              // 35840
#define SM_B1    (SM_B + SM_B_SZ)
#define SM_W2    (SM_B1 + 256)
#define SM_B2    (SM_W2 + 256)
#define SM_TOTAL (SM_B2 + 16)                   // ~108 KB -> 2 CTAs/SM

__device__ __align__(16) float g_Bimg[H * BSTRIDE];   // W1^T padded, [n][k]

__global__ void prep_kernel(const float* __restrict__ W1) {
    for (int i = threadIdx.x; i < H * BSTRIDE; i += blockDim.x) {
        int n = i / BSTRIDE, k = i % BSTRIDE;
        g_Bimg[i] = (k < KTOT) ? W1[k * H + n] : 0.0f;
    }
}

__device__ __forceinline__ uint32_t smem_u32(const void* p) {
    uint32_t a;
    asm("{ .reg .u64 t; cvta.to.shared.u64 t, %1; cvt.u32.u64 %0, t; }" : "=r"(a) : "l"(p));
    return a;
}

__device__ __forceinline__ void ldsm_x4(uint32_t& r0, uint32_t& r1, uint32_t& r2, uint32_t& r3,
                                        uint32_t addr) {
    asm volatile("ldmatrix.sync.aligned.m8n8.x4.shared.b16 {%0,%1,%2,%3}, [%4];"
                 : "=r"(r0), "=r"(r1), "=r"(r2), "=r"(r3) : "r"(addr));
}

__device__ __forceinline__ void mma_tf32(float c[4],
                                         uint32_t a0, uint32_t a1, uint32_t a2, uint32_t a3,
                                         uint32_t b0, uint32_t b1) {
    asm volatile(
        "mma.sync.aligned.m16n8k8.row.col.f32.tf32.tf32.f32 "
        "{%0,%1,%2,%3}, {%4,%5,%6,%7}, {%8,%9}, {%0,%1,%2,%3};"
        : "+f"(c[0]), "+f"(c[1]), "+f"(c[2]), "+f"(c[3])
        : "r"(a0), "r"(a1), "r"(a2), "r"(a3), "r"(b0), "r"(b1));
}

__global__ __launch_bounds__(TPB)
void edge_mlp_mma_kernel(const float* __restrict__ hc,
                         const float* __restrict__ hp,
                         const int*   __restrict__ src,
                         const int*   __restrict__ dst,
                         const float* __restrict__ b1,
                         const float* __restrict__ W2,
                         const float* __restrict__ b2,
                         float*       __restrict__ out,
                         int E)
{
    extern __shared__ char smem[];
    const uint32_t smem_base = smem_u32(smem);
    float* sX  = (float*)(smem + SM_X);
    float* sB1 = (float*)(smem + SM_B1);
    float* sW2 = (float*)(smem + SM_W2);
    float* sB2 = (float*)(smem + SM_B2);

    const int tid  = threadIdx.x;
    const int wid  = tid >> 5;
    const int lane = tid & 31;
    const int e0   = blockIdx.x * TILE_M;

    // ---- B / bias staging (linear copy of prebaked image) ----
    {
        const uint4* s = (const uint4*)g_Bimg;
        uint4* d = (uint4*)(smem + SM_B);
        #pragma unroll 4
        for (int i = tid; i < (H * BSTRIDE) / 4; i += TPB) d[i] = s[i];
    }
    if (tid < H) { sB1[tid] = b1[tid]; sW2[tid] = W2[tid]; }
    if (tid == 0) sB2[0] = b2[0];

    // ---- coalesced gather: 1 LDG.128 per edge per warp ----
    {
        const int lane16  = lane & 15;
        const bool isHead = lane < 16;
        int e  = e0 + wid * 32 + lane;
        int ec = (e < E) ? e : (E - 1);
        int sv = src[ec];
        int tv = dst[ec];

        #pragma unroll 4
        for (int el = 0; el < 32; ++el) {
            int si = __shfl_sync(0xffffffffu, sv, el);
            int ti = __shfl_sync(0xffffffffu, tv, el);
            const float4* p = isHead ? (const float4*)(hc + (size_t)si * D) + lane16
                                     : (const float4*)(hp + (size_t)ti * D) + lane16;
            float4 v = *p;
            int row = wid * 32 + el;
            int col = (isHead ? 0 : D) + lane16 * 4;
            *(float4*)(sX + row * XSTRIDE + col) = v;
        }
    }
    __syncwarp();

    // ---- cosine: thread t owns row t (warp-local) ----
    {
        const float* row = sX + tid * XSTRIDE;
        float nh = 0.f, nt = 0.f, dp = 0.f;
        #pragma unroll
        for (int i = 0; i < D; i += 4) {
            float4 h = *(const float4*)(row + i);
            float4 t = *(const float4*)(row + D + i);
            nh = fmaf(h.x, h.x, nh); nh = fmaf(h.y, h.y, nh);
            nh = fmaf(h.z, h.z, nh); nh = fmaf(h.w, h.w, nh);
            nt = fmaf(t.x, t.x, nt); nt = fmaf(t.y, t.y, nt);
            nt = fmaf(t.z, t.z, nt); nt = fmaf(t.w, t.w, nt);
            dp = fmaf(h.x, t.x, dp); dp = fmaf(h.y, t.y, dp);
            dp = fmaf(h.z, t.z, dp); dp = fmaf(h.w, t.w, dp);
        }
        float nhs = sqrtf(nh), nts = sqrtf(nt);
        float invh = 1.0f / fmaxf(nhs, 1e-12f);
        float invt = 1.0f / fmaxf(nts, 1e-12f);
        float hnn = nhs * invh, tnn = nts * invt;
        float cosv = (dp * invh * invt) / fmaxf(hnn * tnn, 1e-8f);

        float* wrow = sX + tid * XSTRIDE;
        *(float4*)(wrow + 128) = make_float4(cosv, 0.f, 0.f, 0.f);  // col128=cos, 129-131=0
        *(float4*)(wrow + 132) = make_float4(0.f, 0.f, 0.f, 0.f);   // 132-135=0
    }
    __syncthreads();   // B + all X rows ready

    // ---- ldmatrix addresses ----
    const int j = lane >> 3;    // matrix index
    const int r = lane & 7;     // row within matrix
    // A (X): matrix j -> row r + (j&1)*8, byte col (j>>1)*16
    uint32_t aA0 = smem_base + SM_X
                 + (uint32_t)((wid * 32 + r + (j & 1) * 8) * XSTRIDE) * 4u
                 + (uint32_t)(j >> 1) * 16u;
    uint32_t aA1 = aA0 + 16u * XSTRIDE * 4u;
    // B: matrix j -> n = p*16 + r + (j>>1)*8, byte col (j&1)*16
    uint32_t aB[4];
    #pragma unroll
    for (int p = 0; p < 4; ++p)
        aB[p] = smem_base + SM_B
              + (uint32_t)((p * 16 + r + (j >> 1) * 8) * BSTRIDE) * 4u
              + (uint32_t)(j & 1) * 16u;

    float acc[2][8][4];
    #pragma unroll
    for (int mt = 0; mt < 2; ++mt)
        #pragma unroll
        for (int nt = 0; nt < 8; ++nt)
            #pragma unroll
            for (int c = 0; c < 4; ++c) acc[mt][nt][c] = 0.f;

    // ---- mainloop: 17 k-steps ----
    #pragma unroll
    for (int s = 0; s < NKSTEP; ++s) {
        const uint32_t ko = (uint32_t)s * 32u;   // 8 tf32 = 32 bytes per k-step

        uint32_t a0[4], a1[4];
        ldsm_x4(a0[0], a0[1], a0[2], a0[3], aA0 + ko);
        ldsm_x4(a1[0], a1[1], a1[2], a1[3], aA1 + ko);

        uint32_t bf[8][2];
        #pragma unroll
        for (int p = 0; p < 4; ++p) {
            uint32_t r0, r1, r2, r3;
            ldsm_x4(r0, r1, r2, r3, aB[p] + ko);
            bf[2*p][0] = r0; bf[2*p][1] = r1;       // nt = 2p
            bf[2*p+1][0] = r2; bf[2*p+1][1] = r3;   // nt = 2p+1
        }

        #pragma unroll
        for (int nt = 0; nt < 8; ++nt) {
            mma_tf32(acc[0][nt], a0[0], a0[1], a0[2], a0[3], bf[nt][0], bf[nt][1]);
            mma_tf32(acc[1][nt], a1[0], a1[1], a1[2], a1[3], bf[nt][0], bf[nt][1]);
        }
    }

    // ---- epilogue ----
    const int qrow  = lane >> 2;
    const int qlane = lane & 3;
    const float bias2 = sB2[0];
    #pragma unroll
    for (int mt = 0; mt < 2; ++mt) {
        #pragma unroll
        for (int rr = 0; rr < 2; ++rr) {
            float z = 0.f;
            #pragma unroll
            for (int nt = 0; nt < 8; ++nt) {
                int n0 = nt * 8 + 2 * qlane;
                float v0 = acc[mt][nt][2 * rr];
                float v1 = acc[mt][nt][2 * rr + 1];
                float h0 = fmaxf(v0 + sB1[n0], 0.f);
                float h1 = fmaxf(v1 + sB1[n0 + 1], 0.f);
                z = fmaf(h0, sW2[n0], z);
                z = fmaf(h1, sW2[n0 + 1], z);
            }
            z += __shfl_xor_sync(0xffffffffu, z, 1);
            z += __shfl_xor_sync(0xffffffffu, z, 2);
            if (qlane == 0) {
                int eo = e0 + wid * 32 + mt * 16 + rr * 8 + qrow;
                if (eo < E) {
                    float zz = z + bias2;
                    out[eo] = 1.0f / (1.0f + expf(-zz));
                }
            }
        }
    }
}

extern "C" void kernel_launch(void* const* d_in, const int* in_sizes, int n_in,
                              void* d_out, int out_size)
{
    const float* hc  = (const float*)d_in[0];
    const float* hp  = (const float*)d_in[1];
    const int*   src = (const int*)  d_in[2];
    const int*   dst = (const int*)  d_in[3];
    const float* W1  = (const float*)d_in[4];
    const float* b1  = (const float*)d_in[5];
    const float* W2  = (const float*)d_in[6];
    const float* b2  = (const float*)d_in[7];
    float* out = (float*)d_out;

    static int inited = 0;
    if (!inited) {
        cudaFuncSetAttribute(edge_mlp_mma_kernel,
                             cudaFuncAttributeMaxDynamicSharedMemorySize, SM_TOTAL);
        inited = 1;
    }

    int E = in_sizes[2];
    prep_kernel<<<1, 256>>>(W1);
    int blocks = (E + TILE_M - 1) / TILE_M;
    edge_mlp_mma_kernel<<<blocks, TPB, SM_TOTAL>>>(hc, hp, src, dst, b1, W2, b2, out, E);
}

// round 6
// speedup vs baseline: 4.5334x; 1.4081x over previous
#include <cuda_runtime.h>
#include <cstdint>

#define D        64
#define H        64
#define KTOT     129
#define NKSTEP   17          // K padded to 136
#define TILE_M   128
#define TPB      128

#define XSTRIDE  140         // words; phase-of-8 bank pattern conflict-free
#define BSTRIDE  140

// dynamic smem layout (bytes)
#define SM_X     0
#define SM_X_SZ  (TILE_M * XSTRIDE * 4)         // 71680
#define SM_B     (SM_X + SM_X_SZ)
#define SM_B_SZ  (H * BSTRIDE * 4)              // 35840
#define SM_B1    (SM_B + SM_B_SZ)
#define SM_W2    (SM_B1 + 256)
#define SM_B2    (SM_W2 + 256)
#define SM_TOTAL (SM_B2 + 16)                   // ~107.6 KB -> 2 CTAs/SM

__device__ __align__(16) float g_Bimg[H * BSTRIDE];   // W1^T padded, [n][k]

__global__ void prep_kernel(const float* __restrict__ W1) {
    for (int i = threadIdx.x; i < H * BSTRIDE; i += blockDim.x) {
        int n = i / BSTRIDE, k = i % BSTRIDE;
        g_Bimg[i] = (k < KTOT) ? W1[k * H + n] : 0.0f;
    }
}

__device__ __forceinline__ uint32_t smem_u32(const void* p) {
    uint32_t a;
    asm("{ .reg .u64 t; cvta.to.shared.u64 t, %1; cvt.u32.u64 %0, t; }" : "=r"(a) : "l"(p));
    return a;
}

__device__ __forceinline__ void cp16(uint32_t saddr, const void* gaddr) {
    asm volatile("cp.async.cg.shared.global [%0], [%1], 16;" :: "r"(saddr), "l"(gaddr));
}

__device__ __forceinline__ void ldsm_x4(uint32_t& r0, uint32_t& r1, uint32_t& r2, uint32_t& r3,
                                        uint32_t addr) {
    asm volatile("ldmatrix.sync.aligned.m8n8.x4.shared.b16 {%0,%1,%2,%3}, [%4];"
                 : "=r"(r0), "=r"(r1), "=r"(r2), "=r"(r3) : "r"(addr));
}

__device__ __forceinline__ void mma_tf32(float c[4],
                                         uint32_t a0, uint32_t a1, uint32_t a2, uint32_t a3,
                                         uint32_t b0, uint32_t b1) {
    asm volatile(
        "mma.sync.aligned.m16n8k8.row.col.f32.tf32.tf32.f32 "
        "{%0,%1,%2,%3}, {%4,%5,%6,%7}, {%8,%9}, {%0,%1,%2,%3};"
        : "+f"(c[0]), "+f"(c[1]), "+f"(c[2]), "+f"(c[3])
        : "r"(a0), "r"(a1), "r"(a2), "r"(a3), "r"(b0), "r"(b1));
}

__global__ __launch_bounds__(TPB)
void edge_mlp_mma_kernel(const float* __restrict__ hc,
                         const float* __restrict__ hp,
                         const int*   __restrict__ src,
                         const int*   __restrict__ dst,
                         const float* __restrict__ b1,
                         const float* __restrict__ W2,
                         const float* __restrict__ b2,
                         float*       __restrict__ out,
                         int E)
{
    extern __shared__ char smem[];
    const uint32_t smem_base = smem_u32(smem);
    float* sX  = (float*)(smem + SM_X);
    float* sB1 = (float*)(smem + SM_B1);
    float* sW2 = (float*)(smem + SM_W2);
    float* sB2 = (float*)(smem + SM_B2);

    const int tid  = threadIdx.x;
    const int wid  = tid >> 5;
    const int lane = tid & 31;
    const int e0   = blockIdx.x * TILE_M;

    // ---- load edge indices (LDG latency overlapped by B cp.asyncs below) ----
    int e  = e0 + wid * 32 + lane;
    int ec = (e < E) ? e : (E - 1);
    int sv = src[ec];
    int tv = dst[ec];

    // ---- B / bias staging via cp.async (no register round-trip) ----
    {
        const char* gB = (const char*)g_Bimg;
        uint32_t  dB   = smem_base + SM_B;
        // 35840 B / 16 = 2240 chunks; 128 threads -> 17.5 -> loop 18 with guard
        #pragma unroll
        for (int i = 0; i < 18; ++i) {
            int c = i * TPB + tid;
            if (c < (H * BSTRIDE) / 4) cp16(dB + c * 16u, gB + c * 16);
        }
    }
    if (tid < H) { sB1[tid] = b1[tid]; sW2[tid] = W2[tid]; }
    if (tid == 0) sB2[0] = b2[0];

    // ---- coalesced gather via cp.async: 1 LDGSTS per edge per warp ----
    {
        const int lane16  = lane & 15;
        const bool isHead = lane < 16;
        #pragma unroll 8
        for (int el = 0; el < 32; ++el) {
            int si = __shfl_sync(0xffffffffu, sv, el);
            int ti = __shfl_sync(0xffffffffu, tv, el);
            const float* g = isHead ? hc + (size_t)si * D + lane16 * 4
                                    : hp + (size_t)ti * D + lane16 * 4;
            int row = wid * 32 + el;
            int col = (isHead ? 0 : D) + lane16 * 4;
            cp16(smem_base + SM_X + (uint32_t)(row * XSTRIDE + col) * 4u, g);
        }
    }
    asm volatile("cp.async.commit_group;" ::: "memory");
    asm volatile("cp.async.wait_group 0;" ::: "memory");
    __syncthreads();   // B visible to all; X rows are warp-local from here on

    // ---- cosine: thread t owns row t (warp-local) ----
    {
        const float* row = sX + tid * XSTRIDE;
        float nh = 0.f, nt = 0.f, dp = 0.f;
        #pragma unroll
        for (int i = 0; i < D; i += 4) {
            float4 h = *(const float4*)(row + i);
            float4 t = *(const float4*)(row + D + i);
            nh = fmaf(h.x, h.x, nh); nh = fmaf(h.y, h.y, nh);
            nh = fmaf(h.z, h.z, nh); nh = fmaf(h.w, h.w, nh);
            nt = fmaf(t.x, t.x, nt); nt = fmaf(t.y, t.y, nt);
            nt = fmaf(t.z, t.z, nt); nt = fmaf(t.w, t.w, nt);
            dp = fmaf(h.x, t.x, dp); dp = fmaf(h.y, t.y, dp);
            dp = fmaf(h.z, t.z, dp); dp = fmaf(h.w, t.w, dp);
        }
        float nhs = sqrtf(nh), nts = sqrtf(nt);
        float invh = 1.0f / fmaxf(nhs, 1e-12f);
        float invt = 1.0f / fmaxf(nts, 1e-12f);
        float hnn = nhs * invh, tnn = nts * invt;
        float cosv = (dp * invh * invt) / fmaxf(hnn * tnn, 1e-8f);

        float* wrow = sX + tid * XSTRIDE;
        *(float4*)(wrow + 128) = make_float4(cosv, 0.f, 0.f, 0.f);
        *(float4*)(wrow + 132) = make_float4(0.f, 0.f, 0.f, 0.f);
    }
    __syncwarp();      // warp-local X rows ready for this warp's ldmatrix

    // ---- ldmatrix addresses ----
    const int j = lane >> 3;
    const int r = lane & 7;
    uint32_t aA0 = smem_base + SM_X
                 + (uint32_t)((wid * 32 + r + (j & 1) * 8) * XSTRIDE) * 4u
                 + (uint32_t)(j >> 1) * 16u;
    uint32_t aA1 = aA0 + 16u * XSTRIDE * 4u;
    uint32_t aB[4];
    #pragma unroll
    for (int p = 0; p < 4; ++p)
        aB[p] = smem_base + SM_B
              + (uint32_t)((p * 16 + r + (j >> 1) * 8) * BSTRIDE) * 4u
              + (uint32_t)(j & 1) * 16u;

    float acc[2][8][4];
    #pragma unroll
    for (int mt = 0; mt < 2; ++mt)
        #pragma unroll
        for (int nt = 0; nt < 8; ++nt)
            #pragma unroll
            for (int c = 0; c < 4; ++c) acc[mt][nt][c] = 0.f;

    // ---- mainloop: 17 k-steps ----
    #pragma unroll
    for (int s = 0; s < NKSTEP; ++s) {
        const uint32_t ko = (uint32_t)s * 32u;

        uint32_t a0[4], a1[4];
        ldsm_x4(a0[0], a0[1], a0[2], a0[3], aA0 + ko);
        ldsm_x4(a1[0], a1[1], a1[2], a1[3], aA1 + ko);

        uint32_t bf[8][2];
        #pragma unroll
        for (int p = 0; p < 4; ++p) {
            uint32_t r0, r1, r2, r3;
            ldsm_x4(r0, r1, r2, r3, aB[p] + ko);
            bf[2*p][0] = r0; bf[2*p][1] = r1;
            bf[2*p+1][0] = r2; bf[2*p+1][1] = r3;
        }

        #pragma unroll
        for (int nt = 0; nt < 8; ++nt) {
            mma_tf32(acc[0][nt], a0[0], a0[1], a0[2], a0[3], bf[nt][0], bf[nt][1]);
            mma_tf32(acc[1][nt], a1[0], a1[1], a1[2], a1[3], bf[nt][0], bf[nt][1]);
        }
    }

    // ---- epilogue ----
    const int qrow  = lane >> 2;
    const int qlane = lane & 3;
    const float bias2 = sB2[0];
    #pragma unroll
    for (int mt = 0; mt < 2; ++mt) {
        #pragma unroll
        for (int rr = 0; rr < 2; ++rr) {
            float z = 0.f;
            #pragma unroll
            for (int nt = 0; nt < 8; ++nt) {
                int n0 = nt * 8 + 2 * qlane;
                float v0 = acc[mt][nt][2 * rr];
                float v1 = acc[mt][nt][2 * rr + 1];
                float h0 = fmaxf(v0 + sB1[n0], 0.f);
                float h1 = fmaxf(v1 + sB1[n0 + 1], 0.f);
                z = fmaf(h0, sW2[n0], z);
                z = fmaf(h1, sW2[n0 + 1], z);
            }
            z += __shfl_xor_sync(0xffffffffu, z, 1);
            z += __shfl_xor_sync(0xffffffffu, z, 2);
            if (qlane == 0) {
                int eo = e0 + wid * 32 + mt * 16 + rr * 8 + qrow;
                if (eo < E) {
                    float zz = z + bias2;
                    out[eo] = 1.0f / (1.0f + expf(-zz));
                }
            }
        }
    }
}

extern "C" void kernel_launch(void* const* d_in, const int* in_sizes, int n_in,
                              void* d_out, int out_size)
{
    const float* hc  = (const float*)d_in[0];
    const float* hp  = (const float*)d_in[1];
    const int*   src = (const int*)  d_in[2];
    const int*   dst = (const int*)  d_in[3];
    const float* W1  = (const float*)d_in[4];
    const float* b1  = (const float*)d_in[5];
    const float* W2  = (const float*)d_in[6];
    const float* b2  = (const float*)d_in[7];
    float* out = (float*)d_out;

    static int inited = 0;
    if (!inited) {
        cudaFuncSetAttribute(edge_mlp_mma_kernel,
                             cudaFuncAttributeMaxDynamicSharedMemorySize, SM_TOTAL);
        inited = 1;
    }

    int E = in_sizes[2];
    prep_kernel<<<1, 256>>>(W1);
    int blocks = (E + TILE_M - 1) / TILE_M;
    edge_mlp_mma_kernel<<<blocks, TPB, SM_TOTAL>>>(hc, hp, src, dst, b1, W2, b2, out, E);
}